// round 4
// baseline (speedup 1.0000x reference)
#include <cuda_runtime.h>
#include <math.h>

// ---------------------------------------------------------------------------
// FractalDecoderV6 — fused single kernel, fp32, f32x2-packed FMA.
// R3 fix: GEMM2 contracts full K=512 (32 tiles), prefetch schedule updated.
// ---------------------------------------------------------------------------

#define Bn     16384
#define Ln     8
#define En     8
#define Sn     16384
#define Kn     32
#define HID    256
#define FFd    512
#define Tn     48
#define LATn   32
#define VOCAB  256
#define IN_DIM 161
#define FST    168

#define MROWS  32
#define NTHR   256
#define KT     16

typedef unsigned long long u64;

__device__ __forceinline__ void fma2(u64 &d, u64 a, u64 b) {
    asm volatile("fma.rn.f32x2 %0, %1, %2, %0;" : "+l"(d) : "l"(a), "l"(b));
}
__device__ __forceinline__ u64 pack2(float x, float y) {
    u64 r; asm("mov.b64 %0, {%1, %2};" : "=l"(r) : "f"(x), "f"(y)); return r;
}
__device__ __forceinline__ float2 unpack2(u64 v) {
    float2 f; asm("mov.b64 {%0, %1}, %2;" : "=f"(f.x), "=f"(f.y) : "l"(v)); return f;
}
__device__ __forceinline__ void cp16(float* sdst, const float* gsrc) {
    unsigned s = (unsigned)__cvta_generic_to_shared(sdst);
    asm volatile("cp.async.cg.shared.global [%0], [%1], 16;" :: "r"(s), "l"(gsrc));
}
__device__ __forceinline__ void cp_commit() { asm volatile("cp.async.commit_group;"); }
__device__ __forceinline__ void cp_wait1()  { asm volatile("cp.async.wait_group 1;"); }
__device__ __forceinline__ void cp_wait0()  { asm volatile("cp.async.wait_group 0;"); }

__device__ __forceinline__ float gelu_exact(float v) {
    return 0.5f * v * (1.0f + erff(v * 0.70710678118654752f));
}
__device__ __forceinline__ float tanh_acc(float x) {   // fast-math-proof tanh
    float a  = fabsf(x);
    float em = expm1f(-2.0f * a);
    float t  = -em / (2.0f + em);
    return copysignf(t, x);
}

__global__ void __launch_bounds__(NTHR, 1)
fractal_kernel(const float* __restrict__ x,   const float* __restrict__ z,
               const float* __restrict__ tbl,
               const float* __restrict__ W1,  const float* __restrict__ b1,
               const float* __restrict__ W2,  const float* __restrict__ b2,
               const float* __restrict__ Wf1, const float* __restrict__ bf1,
               const float* __restrict__ Wf2, const float* __restrict__ bf2,
               const float* __restrict__ Wo,  const float* __restrict__ bo,
               const int*   __restrict__ resolutions,
               const float* __restrict__ freqs,
               float* __restrict__ out)
{
    extern __shared__ float sm[];
    float* hs2 = sm;            // 32*256*2 floats (h duplicated pairs)
    float* gs  = sm + 16384;    // 32*512 floats   (g / feats)
    float* wb  = sm + 32768;    // 2 * 8192 floats (weight double buffer)

    const int t     = threadIdx.x;
    const int r0    = blockIdx.x * MROWS;
    const int rg    = t >> 6;
    const int rbase = rg * 8;
    const int ct    = t & 63;

    // ---------------- feature stage (feats alias gs, stride FST) ----------------
    {
        int   row = t >> 3;
        int   sub = t & 7;
        int   gr  = r0 + row;
        float xn  = fminf(fmaxf(x[gr], 0.0f), 1.0f);
        float* f  = gs + row * FST;
        if (sub == 0) f[0] = xn;
        float a = 6.2831855f * xn;
        #pragma unroll
        for (int q = 0; q < 4; q++) {
            int fi = sub * 4 + q;
            float arg = a * freqs[fi];
            double s, c;
            sincos((double)arg, &s, &c);
            f[1 + fi]      = (float)s;
            f[1 + Kn + fi] = (float)c;
        }
        {
            int   R  = resolutions[sub];
            float tf = xn * (float)(R - 1);
            int   i0 = (int)floorf(tf);
            int   i1 = min(i0 + 1, R - 1);
            float w  = tf - (float)i0;
            unsigned lt = (unsigned)(sub * 19349663);
            int h0 = (int)((((unsigned)i0 * 73856093u) ^ lt) & 16383u);
            int h1 = (int)((((unsigned)i1 * 73856093u) ^ lt) & 16383u);
            const float* e0 = tbl + ((size_t)sub * Sn + h0) * En;
            const float* e1 = tbl + ((size_t)sub * Sn + h1) * En;
            #pragma unroll
            for (int e = 0; e < En; e++)
                f[1 + 2 * Kn + sub * En + e] = e0[e] * (1.0f - w) + e1[e] * w;
        }
        #pragma unroll
        for (int q = 0; q < 4; q++)
            f[1 + 2 * Kn + Ln * En + sub * 4 + q] = z[(size_t)gr * LATn + sub * 4 + q];
    }
    __syncthreads();

    // ---------------- bias registers ----------------
    float2 bf1r[4], bf2r[2], b1r[2], b2r[2], bor[2];
    #pragma unroll
    for (int j = 0; j < 4; j++) bf1r[j] = *(const float2*)&bf1[2 * ct + 128 * j];
    #pragma unroll
    for (int j = 0; j < 2; j++) {
        bf2r[j] = *(const float2*)&bf2[2 * ct + 128 * j];
        b1r[j]  = *(const float2*)&b1 [2 * ct + 128 * j];
        b2r[j]  = *(const float2*)&b2 [2 * ct + 128 * j];
        bor[j]  = *(const float2*)&bo [2 * ct + 128 * j];
    }

    // ---------------- GEMM0: h1 = gelu(feats @ W1 + b1) ----------------
    {
        u64 acc[8][2];
        #pragma unroll
        for (int r = 0; r < 8; r++) { acc[r][0] = 0ull; acc[r][1] = 0ull; }
        for (int k = 0; k < IN_DIM; k++) {
            u64 wA = *(const u64*)&W1[k * HID + 2 * ct];
            u64 wB = *(const u64*)&W1[k * HID + 128 + 2 * ct];
            #pragma unroll
            for (int r = 0; r < 8; r++) {
                float hv = gs[(rbase + r) * FST + k];
                u64 hp = pack2(hv, hv);
                fma2(acc[r][0], hp, wA);
                fma2(acc[r][1], hp, wB);
            }
        }
        __syncthreads();
        #pragma unroll
        for (int r = 0; r < 8; r++)
            #pragma unroll
            for (int j = 0; j < 2; j++) {
                float2 v = unpack2(acc[r][j]);
                float g0 = gelu_exact(v.x + b1r[j].x);
                float g1 = gelu_exact(v.y + b1r[j].y);
                *(float4*)&hs2[((rbase + r) * HID + 2 * ct + 128 * j) * 2] =
                    make_float4(g0, g0, g1, g1);
            }
    }
    __syncthreads();

    float2 hreg[8][2];   // fp32 carried state (this thread's rows/cols)

    // ---------------- h = gelu(h1 @ W2 + b2) ----------------
    {
        u64 acc[8][2];
        #pragma unroll
        for (int r = 0; r < 8; r++) { acc[r][0] = 0ull; acc[r][1] = 0ull; }
        for (int k = 0; k < HID; k++) {
            u64 wA = *(const u64*)&W2[k * HID + 2 * ct];
            u64 wB = *(const u64*)&W2[k * HID + 128 + 2 * ct];
            #pragma unroll
            for (int r = 0; r < 8; r++) {
                float hv = hs2[((rbase + r) * HID + k) * 2];
                u64 hp = pack2(hv, hv);
                fma2(acc[r][0], hp, wA);
                fma2(acc[r][1], hp, wB);
            }
        }
        float4 res[8][2];
        #pragma unroll
        for (int r = 0; r < 8; r++)
            #pragma unroll
            for (int j = 0; j < 2; j++) {
                float2 v = unpack2(acc[r][j]);
                float h0 = gelu_exact(v.x + b2r[j].x);
                float h1 = gelu_exact(v.y + b2r[j].y);
                hreg[r][j] = make_float2(h0, h1);
                res[r][j]  = make_float4(h0, h0, h1, h1);
            }
        __syncthreads();
        #pragma unroll
        for (int r = 0; r < 8; r++)
            #pragma unroll
            for (int j = 0; j < 2; j++)
                *(float4*)&hs2[((rbase + r) * HID + 2 * ct + 128 * j) * 2] = res[r][j];
    }
    __syncthreads();

    // prime pipeline: Wf1 tile 0 -> buf 0
    for (int c = t; c < (KT * FFd) >> 2; c += NTHR) cp16(wb + c * 4, Wf1 + c * 4);
    cp_commit();

    // ---------------- 48-step scan ----------------
    #pragma unroll 1
    for (int step = 0; step < Tn; step++) {
        // ---- GEMM1: g = gelu(h @ Wf1 + bf1), K = 256 -> 16 tiles ----
        u64 acc1[8][4];
        #pragma unroll
        for (int r = 0; r < 8; r++)
            #pragma unroll
            for (int j = 0; j < 4; j++) acc1[r][j] = 0ull;

        #pragma unroll 1
        for (int kt = 0; kt < 16; kt++) {
            const float* src; int nf;
            if (kt < 15) { src = Wf1 + (kt + 1) * KT * FFd; nf = KT * FFd; }
            else         { src = Wf2;                       nf = KT * HID; }  // Wf2 tile0
            float* dst = wb + ((kt + 1) & 1) * 8192;
            for (int c = t; c < (nf >> 2); c += NTHR) cp16(dst + c * 4, src + c * 4);
            cp_commit();
            cp_wait1();
            __syncthreads();

            const float* wp = wb + (kt & 1) * 8192;
            const int k0 = kt * KT;
            #pragma unroll
            for (int kk = 0; kk < KT; kk++) {
                u64 w[4];
                #pragma unroll
                for (int j = 0; j < 4; j++)
                    w[j] = *(const u64*)&wp[kk * FFd + 2 * ct + 128 * j];
                #pragma unroll
                for (int r = 0; r < 8; r++) {
                    u64 hp = *(const u64*)&hs2[((rbase + r) * HID + k0 + kk) * 2];
                    fma2(acc1[r][0], hp, w[0]);
                    fma2(acc1[r][1], hp, w[1]);
                    fma2(acc1[r][2], hp, w[2]);
                    fma2(acc1[r][3], hp, w[3]);
                }
            }
            __syncthreads();
        }
        #pragma unroll
        for (int r = 0; r < 8; r++)
            #pragma unroll
            for (int j = 0; j < 4; j++) {
                float2 v = unpack2(acc1[r][j]);
                float g0 = gelu_exact(v.x + bf1r[j].x);
                float g1 = gelu_exact(v.y + bf1r[j].y);
                *(float2*)&gs[(rbase + r) * FFd + 2 * ct + 128 * j] = make_float2(g0, g1);
            }
        __syncthreads();

        // ---- GEMM2: u = tanh(g @ Wf2 + bf2), K = 512 -> 32 tiles (R3 FIX) ----
        u64 acc2[8][2];
        #pragma unroll
        for (int r = 0; r < 8; r++) { acc2[r][0] = 0ull; acc2[r][1] = 0ull; }

        #pragma unroll 1
        for (int kt = 0; kt < 32; kt++) {
            const float* src; int nf;
            if (kt < 31) { src = Wf2 + (kt + 1) * KT * HID; nf = KT * HID; }
            else         { src = Wf1;                       nf = KT * FFd; }  // next step tile0
            float* dst = wb + ((kt + 1) & 1) * 8192;
            for (int c = t; c < (nf >> 2); c += NTHR) cp16(dst + c * 4, src + c * 4);
            cp_commit();
            cp_wait1();
            __syncthreads();

            const float* wp = wb + (kt & 1) * 8192;
            const int k0 = kt * KT;
            #pragma unroll
            for (int kk2 = 0; kk2 < KT / 2; kk2++) {
                u64 wA[2], wB[2];
                #pragma unroll
                for (int j = 0; j < 2; j++) {
                    wA[j] = *(const u64*)&wp[(2 * kk2)     * HID + 2 * ct + 128 * j];
                    wB[j] = *(const u64*)&wp[(2 * kk2 + 1) * HID + 2 * ct + 128 * j];
                }
                #pragma unroll
                for (int r = 0; r < 8; r++) {
                    float2 h2 = *(const float2*)&gs[(rbase + r) * FFd + k0 + 2 * kk2];
                    u64 hA = pack2(h2.x, h2.x);
                    u64 hB = pack2(h2.y, h2.y);
                    fma2(acc2[r][0], hA, wA[0]);
                    fma2(acc2[r][1], hA, wA[1]);
                    fma2(acc2[r][0], hB, wB[0]);
                    fma2(acc2[r][1], hB, wB[1]);
                }
            }
            __syncthreads();
        }
        float4 newv[8][2];
        #pragma unroll
        for (int r = 0; r < 8; r++)
            #pragma unroll
            for (int j = 0; j < 2; j++) {
                float2 v = unpack2(acc2[r][j]);
                float u0 = tanh_acc(v.x + bf2r[j].x);
                float u1 = tanh_acc(v.y + bf2r[j].y);
                float h0 = 0.5f * hreg[r][j].x + 0.5f * u0;
                float h1 = 0.5f * hreg[r][j].y + 0.5f * u1;
                hreg[r][j] = make_float2(h0, h1);
                newv[r][j] = make_float4(h0, h0, h1, h1);
            }
        __syncthreads();
        #pragma unroll
        for (int r = 0; r < 8; r++)
            #pragma unroll
            for (int j = 0; j < 2; j++)
                *(float4*)&hs2[((rbase + r) * HID + 2 * ct + 128 * j) * 2] = newv[r][j];
        __syncthreads();
    }
    cp_wait0();

    // ---------------- final: out = h @ Wo + bo ----------------
    {
        u64 acc[8][2];
        #pragma unroll
        for (int r = 0; r < 8; r++) { acc[r][0] = 0ull; acc[r][1] = 0ull; }
        for (int k = 0; k < HID; k++) {
            u64 wA = *(const u64*)&Wo[k * VOCAB + 2 * ct];
            u64 wB = *(const u64*)&Wo[k * VOCAB + 128 + 2 * ct];
            #pragma unroll
            for (int r = 0; r < 8; r++) {
                float hv = hs2[((rbase + r) * HID + k) * 2];
                u64 hp = pack2(hv, hv);
                fma2(acc[r][0], hp, wA);
                fma2(acc[r][1], hp, wB);
            }
        }
        #pragma unroll
        for (int r = 0; r < 8; r++)
            #pragma unroll
            for (int j = 0; j < 2; j++) {
                float2 v = unpack2(acc[r][j]);
                v.x += bor[j].x;
                v.y += bor[j].y;
                *(float2*)&out[(size_t)(r0 + rbase + r) * VOCAB + 2 * ct + 128 * j] = v;
            }
    }
}

extern "C" void kernel_launch(void* const* d_in, const int* in_sizes, int n_in,
                              void* d_out, int out_size)
{
    (void)out_size;
    // Size-keyed input resolution (robust to metadata ordering conventions
    // that preserve relative order of equal-sized inputs).
    const float *x=0, *z=0, *tbl=0, *W1=0, *b1=0, *W2=0, *b2=0,
                *Wf1=0, *bf1=0, *Wf2=0, *bf2=0, *Wo=0, *bo=0, *frq=0;
    const int* res = 0;
    int c65536 = 0, c131072 = 0, c256 = 0;
    for (int i = 0; i < n_in; i++) {
        const void* p = d_in[i];
        switch (in_sizes[i]) {
            case 16384:   x   = (const float*)p; break;
            case 524288:  z   = (const float*)p; break;
            case 1048576: tbl = (const float*)p; break;
            case 41216:   W1  = (const float*)p; break;
            case 512:     bf1 = (const float*)p; break;
            case 8:       res = (const int*)p;   break;
            case 32:      frq = (const float*)p; break;
            case 65536:   if (c65536++  == 0) W2  = (const float*)p; else Wo  = (const float*)p; break;
            case 131072:  if (c131072++ == 0) Wf1 = (const float*)p; else Wf2 = (const float*)p; break;
            case 256:
                switch (c256++) {
                    case 0: b1  = (const float*)p; break;
                    case 1: b2  = (const float*)p; break;
                    case 2: bf2 = (const float*)p; break;
                    default: bo = (const float*)p; break;
                }
                break;
            default: break;
        }
    }
    float* out = (float*)d_out;

    const int smem = 48 * 1024 * 4;   // 196608 bytes
    cudaFuncSetAttribute(fractal_kernel, cudaFuncAttributeMaxDynamicSharedMemorySize, smem);
    fractal_kernel<<<Bn / MROWS, NTHR, smem>>>(x, z, tbl, W1, b1, W2, b2,
                                               Wf1, bf1, Wf2, bf2, Wo, bo,
                                               res, frq, out);
}

// round 5
// speedup vs baseline: 1.0008x; 1.0008x over previous
#include <cuda_runtime.h>
#include <math.h>

// ---------------------------------------------------------------------------
// FractalDecoderV6 — fused single kernel, fp32, f32x2-packed FMA.
// R3 fix: GEMM2 contracts full K=512 (32 tiles), prefetch schedule updated.
// ---------------------------------------------------------------------------

#define Bn     16384
#define Ln     8
#define En     8
#define Sn     16384
#define Kn     32
#define HID    256
#define FFd    512
#define Tn     48
#define LATn   32
#define VOCAB  256
#define IN_DIM 161
#define FST    168

#define MROWS  32
#define NTHR   256
#define KT     16

typedef unsigned long long u64;

__device__ __forceinline__ void fma2(u64 &d, u64 a, u64 b) {
    asm volatile("fma.rn.f32x2 %0, %1, %2, %0;" : "+l"(d) : "l"(a), "l"(b));
}
__device__ __forceinline__ u64 pack2(float x, float y) {
    u64 r; asm("mov.b64 %0, {%1, %2};" : "=l"(r) : "f"(x), "f"(y)); return r;
}
__device__ __forceinline__ float2 unpack2(u64 v) {
    float2 f; asm("mov.b64 {%0, %1}, %2;" : "=f"(f.x), "=f"(f.y) : "l"(v)); return f;
}
__device__ __forceinline__ void cp16(float* sdst, const float* gsrc) {
    unsigned s = (unsigned)__cvta_generic_to_shared(sdst);
    asm volatile("cp.async.cg.shared.global [%0], [%1], 16;" :: "r"(s), "l"(gsrc));
}
__device__ __forceinline__ void cp_commit() { asm volatile("cp.async.commit_group;"); }
__device__ __forceinline__ void cp_wait1()  { asm volatile("cp.async.wait_group 1;"); }
__device__ __forceinline__ void cp_wait0()  { asm volatile("cp.async.wait_group 0;"); }

__device__ __forceinline__ float gelu_exact(float v) {
    return 0.5f * v * (1.0f + erff(v * 0.70710678118654752f));
}
__device__ __forceinline__ float tanh_acc(float x) {   // fast-math-proof tanh
    float a  = fabsf(x);
    float em = expm1f(-2.0f * a);
    float t  = -em / (2.0f + em);
    return copysignf(t, x);
}

__global__ void __launch_bounds__(NTHR, 1)
fractal_kernel(const float* __restrict__ x,   const float* __restrict__ z,
               const float* __restrict__ tbl,
               const float* __restrict__ W1,  const float* __restrict__ b1,
               const float* __restrict__ W2,  const float* __restrict__ b2,
               const float* __restrict__ Wf1, const float* __restrict__ bf1,
               const float* __restrict__ Wf2, const float* __restrict__ bf2,
               const float* __restrict__ Wo,  const float* __restrict__ bo,
               const int*   __restrict__ resolutions,
               const float* __restrict__ freqs,
               float* __restrict__ out)
{
    extern __shared__ float sm[];
    float* hs2 = sm;            // 32*256*2 floats (h duplicated pairs)
    float* gs  = sm + 16384;    // 32*512 floats   (g / feats)
    float* wb  = sm + 32768;    // 2 * 8192 floats (weight double buffer)

    const int t     = threadIdx.x;
    const int r0    = blockIdx.x * MROWS;
    const int rg    = t >> 6;
    const int rbase = rg * 8;
    const int ct    = t & 63;

    // ---------------- feature stage (feats alias gs, stride FST) ----------------
    {
        int   row = t >> 3;
        int   sub = t & 7;
        int   gr  = r0 + row;
        float xn  = fminf(fmaxf(x[gr], 0.0f), 1.0f);
        float* f  = gs + row * FST;
        if (sub == 0) f[0] = xn;
        float a = 6.2831855f * xn;
        #pragma unroll
        for (int q = 0; q < 4; q++) {
            int fi = sub * 4 + q;
            float arg = a * freqs[fi];
            double s, c;
            sincos((double)arg, &s, &c);
            f[1 + fi]      = (float)s;
            f[1 + Kn + fi] = (float)c;
        }
        {
            int   R  = resolutions[sub];
            float tf = xn * (float)(R - 1);
            int   i0 = (int)floorf(tf);
            int   i1 = min(i0 + 1, R - 1);
            float w  = tf - (float)i0;
            unsigned lt = (unsigned)(sub * 19349663);
            int h0 = (int)((((unsigned)i0 * 73856093u) ^ lt) & 16383u);
            int h1 = (int)((((unsigned)i1 * 73856093u) ^ lt) & 16383u);
            const float* e0 = tbl + ((size_t)sub * Sn + h0) * En;
            const float* e1 = tbl + ((size_t)sub * Sn + h1) * En;
            #pragma unroll
            for (int e = 0; e < En; e++)
                f[1 + 2 * Kn + sub * En + e] = e0[e] * (1.0f - w) + e1[e] * w;
        }
        #pragma unroll
        for (int q = 0; q < 4; q++)
            f[1 + 2 * Kn + Ln * En + sub * 4 + q] = z[(size_t)gr * LATn + sub * 4 + q];
    }
    __syncthreads();

    // ---------------- bias registers ----------------
    float2 bf1r[4], bf2r[2], b1r[2], b2r[2], bor[2];
    #pragma unroll
    for (int j = 0; j < 4; j++) bf1r[j] = *(const float2*)&bf1[2 * ct + 128 * j];
    #pragma unroll
    for (int j = 0; j < 2; j++) {
        bf2r[j] = *(const float2*)&bf2[2 * ct + 128 * j];
        b1r[j]  = *(const float2*)&b1 [2 * ct + 128 * j];
        b2r[j]  = *(const float2*)&b2 [2 * ct + 128 * j];
        bor[j]  = *(const float2*)&bo [2 * ct + 128 * j];
    }

    // ---------------- GEMM0: h1 = gelu(feats @ W1 + b1) ----------------
    {
        u64 acc[8][2];
        #pragma unroll
        for (int r = 0; r < 8; r++) { acc[r][0] = 0ull; acc[r][1] = 0ull; }
        for (int k = 0; k < IN_DIM; k++) {
            u64 wA = *(const u64*)&W1[k * HID + 2 * ct];
            u64 wB = *(const u64*)&W1[k * HID + 128 + 2 * ct];
            #pragma unroll
            for (int r = 0; r < 8; r++) {
                float hv = gs[(rbase + r) * FST + k];
                u64 hp = pack2(hv, hv);
                fma2(acc[r][0], hp, wA);
                fma2(acc[r][1], hp, wB);
            }
        }
        __syncthreads();
        #pragma unroll
        for (int r = 0; r < 8; r++)
            #pragma unroll
            for (int j = 0; j < 2; j++) {
                float2 v = unpack2(acc[r][j]);
                float g0 = gelu_exact(v.x + b1r[j].x);
                float g1 = gelu_exact(v.y + b1r[j].y);
                *(float4*)&hs2[((rbase + r) * HID + 2 * ct + 128 * j) * 2] =
                    make_float4(g0, g0, g1, g1);
            }
    }
    __syncthreads();

    float2 hreg[8][2];   // fp32 carried state (this thread's rows/cols)

    // ---------------- h = gelu(h1 @ W2 + b2) ----------------
    {
        u64 acc[8][2];
        #pragma unroll
        for (int r = 0; r < 8; r++) { acc[r][0] = 0ull; acc[r][1] = 0ull; }
        for (int k = 0; k < HID; k++) {
            u64 wA = *(const u64*)&W2[k * HID + 2 * ct];
            u64 wB = *(const u64*)&W2[k * HID + 128 + 2 * ct];
            #pragma unroll
            for (int r = 0; r < 8; r++) {
                float hv = hs2[((rbase + r) * HID + k) * 2];
                u64 hp = pack2(hv, hv);
                fma2(acc[r][0], hp, wA);
                fma2(acc[r][1], hp, wB);
            }
        }
        float4 res[8][2];
        #pragma unroll
        for (int r = 0; r < 8; r++)
            #pragma unroll
            for (int j = 0; j < 2; j++) {
                float2 v = unpack2(acc[r][j]);
                float h0 = gelu_exact(v.x + b2r[j].x);
                float h1 = gelu_exact(v.y + b2r[j].y);
                hreg[r][j] = make_float2(h0, h1);
                res[r][j]  = make_float4(h0, h0, h1, h1);
            }
        __syncthreads();
        #pragma unroll
        for (int r = 0; r < 8; r++)
            #pragma unroll
            for (int j = 0; j < 2; j++)
                *(float4*)&hs2[((rbase + r) * HID + 2 * ct + 128 * j) * 2] = res[r][j];
    }
    __syncthreads();

    // prime pipeline: Wf1 tile 0 -> buf 0
    for (int c = t; c < (KT * FFd) >> 2; c += NTHR) cp16(wb + c * 4, Wf1 + c * 4);
    cp_commit();

    // ---------------- 48-step scan ----------------
    #pragma unroll 1
    for (int step = 0; step < Tn; step++) {
        // ---- GEMM1: g = gelu(h @ Wf1 + bf1), K = 256 -> 16 tiles ----
        u64 acc1[8][4];
        #pragma unroll
        for (int r = 0; r < 8; r++)
            #pragma unroll
            for (int j = 0; j < 4; j++) acc1[r][j] = 0ull;

        #pragma unroll 1
        for (int kt = 0; kt < 16; kt++) {
            const float* src; int nf;
            if (kt < 15) { src = Wf1 + (kt + 1) * KT * FFd; nf = KT * FFd; }
            else         { src = Wf2;                       nf = KT * HID; }  // Wf2 tile0
            float* dst = wb + ((kt + 1) & 1) * 8192;
            for (int c = t; c < (nf >> 2); c += NTHR) cp16(dst + c * 4, src + c * 4);
            cp_commit();
            cp_wait1();
            __syncthreads();

            const float* wp = wb + (kt & 1) * 8192;
            const int k0 = kt * KT;
            #pragma unroll
            for (int kk = 0; kk < KT; kk++) {
                u64 w[4];
                #pragma unroll
                for (int j = 0; j < 4; j++)
                    w[j] = *(const u64*)&wp[kk * FFd + 2 * ct + 128 * j];
                #pragma unroll
                for (int r = 0; r < 8; r++) {
                    u64 hp = *(const u64*)&hs2[((rbase + r) * HID + k0 + kk) * 2];
                    fma2(acc1[r][0], hp, w[0]);
                    fma2(acc1[r][1], hp, w[1]);
                    fma2(acc1[r][2], hp, w[2]);
                    fma2(acc1[r][3], hp, w[3]);
                }
            }
            __syncthreads();
        }
        #pragma unroll
        for (int r = 0; r < 8; r++)
            #pragma unroll
            for (int j = 0; j < 4; j++) {
                float2 v = unpack2(acc1[r][j]);
                float g0 = gelu_exact(v.x + bf1r[j].x);
                float g1 = gelu_exact(v.y + bf1r[j].y);
                *(float2*)&gs[(rbase + r) * FFd + 2 * ct + 128 * j] = make_float2(g0, g1);
            }
        __syncthreads();

        // ---- GEMM2: u = tanh(g @ Wf2 + bf2), K = 512 -> 32 tiles (R3 FIX) ----
        u64 acc2[8][2];
        #pragma unroll
        for (int r = 0; r < 8; r++) { acc2[r][0] = 0ull; acc2[r][1] = 0ull; }

        #pragma unroll 1
        for (int kt = 0; kt < 32; kt++) {
            const float* src; int nf;
            if (kt < 31) { src = Wf2 + (kt + 1) * KT * HID; nf = KT * HID; }
            else         { src = Wf1;                       nf = KT * FFd; }  // next step tile0
            float* dst = wb + ((kt + 1) & 1) * 8192;
            for (int c = t; c < (nf >> 2); c += NTHR) cp16(dst + c * 4, src + c * 4);
            cp_commit();
            cp_wait1();
            __syncthreads();

            const float* wp = wb + (kt & 1) * 8192;
            const int k0 = kt * KT;
            #pragma unroll
            for (int kk2 = 0; kk2 < KT / 2; kk2++) {
                u64 wA[2], wB[2];
                #pragma unroll
                for (int j = 0; j < 2; j++) {
                    wA[j] = *(const u64*)&wp[(2 * kk2)     * HID + 2 * ct + 128 * j];
                    wB[j] = *(const u64*)&wp[(2 * kk2 + 1) * HID + 2 * ct + 128 * j];
                }
                #pragma unroll
                for (int r = 0; r < 8; r++) {
                    float2 h2 = *(const float2*)&gs[(rbase + r) * FFd + k0 + 2 * kk2];
                    u64 hA = pack2(h2.x, h2.x);
                    u64 hB = pack2(h2.y, h2.y);
                    fma2(acc2[r][0], hA, wA[0]);
                    fma2(acc2[r][1], hA, wA[1]);
                    fma2(acc2[r][0], hB, wB[0]);
                    fma2(acc2[r][1], hB, wB[1]);
                }
            }
            __syncthreads();
        }
        float4 newv[8][2];
        #pragma unroll
        for (int r = 0; r < 8; r++)
            #pragma unroll
            for (int j = 0; j < 2; j++) {
                float2 v = unpack2(acc2[r][j]);
                float u0 = tanh_acc(v.x + bf2r[j].x);
                float u1 = tanh_acc(v.y + bf2r[j].y);
                float h0 = 0.5f * hreg[r][j].x + 0.5f * u0;
                float h1 = 0.5f * hreg[r][j].y + 0.5f * u1;
                hreg[r][j] = make_float2(h0, h1);
                newv[r][j] = make_float4(h0, h0, h1, h1);
            }
        __syncthreads();
        #pragma unroll
        for (int r = 0; r < 8; r++)
            #pragma unroll
            for (int j = 0; j < 2; j++)
                *(float4*)&hs2[((rbase + r) * HID + 2 * ct + 128 * j) * 2] = newv[r][j];
        __syncthreads();
    }
    cp_wait0();

    // ---------------- final: out = h @ Wo + bo ----------------
    {
        u64 acc[8][2];
        #pragma unroll
        for (int r = 0; r < 8; r++) { acc[r][0] = 0ull; acc[r][1] = 0ull; }
        for (int k = 0; k < HID; k++) {
            u64 wA = *(const u64*)&Wo[k * VOCAB + 2 * ct];
            u64 wB = *(const u64*)&Wo[k * VOCAB + 128 + 2 * ct];
            #pragma unroll
            for (int r = 0; r < 8; r++) {
                float hv = hs2[((rbase + r) * HID + k) * 2];
                u64 hp = pack2(hv, hv);
                fma2(acc[r][0], hp, wA);
                fma2(acc[r][1], hp, wB);
            }
        }
        #pragma unroll
        for (int r = 0; r < 8; r++)
            #pragma unroll
            for (int j = 0; j < 2; j++) {
                float2 v = unpack2(acc[r][j]);
                v.x += bor[j].x;
                v.y += bor[j].y;
                *(float2*)&out[(size_t)(r0 + rbase + r) * VOCAB + 2 * ct + 128 * j] = v;
            }
    }
}

extern "C" void kernel_launch(void* const* d_in, const int* in_sizes, int n_in,
                              void* d_out, int out_size)
{
    (void)out_size;
    // Size-keyed input resolution (robust to metadata ordering conventions
    // that preserve relative order of equal-sized inputs).
    const float *x=0, *z=0, *tbl=0, *W1=0, *b1=0, *W2=0, *b2=0,
                *Wf1=0, *bf1=0, *Wf2=0, *bf2=0, *Wo=0, *bo=0, *frq=0;
    const int* res = 0;
    int c65536 = 0, c131072 = 0, c256 = 0;
    for (int i = 0; i < n_in; i++) {
        const void* p = d_in[i];
        switch (in_sizes[i]) {
            case 16384:   x   = (const float*)p; break;
            case 524288:  z   = (const float*)p; break;
            case 1048576: tbl = (const float*)p; break;
            case 41216:   W1  = (const float*)p; break;
            case 512:     bf1 = (const float*)p; break;
            case 8:       res = (const int*)p;   break;
            case 32:      frq = (const float*)p; break;
            case 65536:   if (c65536++  == 0) W2  = (const float*)p; else Wo  = (const float*)p; break;
            case 131072:  if (c131072++ == 0) Wf1 = (const float*)p; else Wf2 = (const float*)p; break;
            case 256:
                switch (c256++) {
                    case 0: b1  = (const float*)p; break;
                    case 1: b2  = (const float*)p; break;
                    case 2: bf2 = (const float*)p; break;
                    default: bo = (const float*)p; break;
                }
                break;
            default: break;
        }
    }
    float* out = (float*)d_out;

    const int smem = 48 * 1024 * 4;   // 196608 bytes
    cudaFuncSetAttribute(fractal_kernel, cudaFuncAttributeMaxDynamicSharedMemorySize, smem);
    fractal_kernel<<<Bn / MROWS, NTHR, smem>>>(x, z, tbl, W1, b1, W2, b2,
                                               Wf1, bf1, Wf2, bf2, Wo, bo,
                                               res, frq, out);
}